// round 1
// baseline (speedup 1.0000x reference)
#include <cuda_runtime.h>

#define N 8192
#define D 128
#define BM 128
#define BN 128
#define THREADS 512

// Scratch (no allocations allowed): transposed z and row squared-norms.
__device__ float g_zT[D * N];   // 4 MB, k-major: g_zT[k*N + i] = z[i][k]
__device__ float g_sq[N];

// ---------------------------------------------------------------------------
// Prep: transpose z into g_zT and compute sq[i] = ||z_i||^2.
// One row per block, 128 threads.
// ---------------------------------------------------------------------------
__global__ void prep_kernel(const float* __restrict__ z) {
    int row = blockIdx.x;
    int t = threadIdx.x;            // 0..127 == k
    float v = z[row * D + t];
    g_zT[t * N + row] = v;          // scattered 4B writes: 32MB of sectors, ~5us total
    float s = v * v;
    #pragma unroll
    for (int off = 16; off > 0; off >>= 1)
        s += __shfl_xor_sync(0xffffffffu, s, off);
    __shared__ float ws[4];
    if ((t & 31) == 0) ws[t >> 5] = s;
    __syncthreads();
    if (t == 0) g_sq[row] = ws[0] + ws[1] + ws[2] + ws[3];
}

// ---------------------------------------------------------------------------
// Packed fp32 helpers (fma.rn.f32x2 — FFMA2, 2x fp32 FMA throughput).
// ---------------------------------------------------------------------------
__device__ __forceinline__ unsigned long long pack2(float a) {
    unsigned long long r;
    asm("mov.b64 %0, {%1, %1};" : "=l"(r) : "r"(__float_as_uint(a)));
    return r;
}
__device__ __forceinline__ void ffma2(unsigned long long& c,
                                      unsigned long long a,
                                      unsigned long long b) {
    asm("fma.rn.f32x2 %0, %1, %2, %0;" : "+l"(c) : "l"(a), "l"(b));
}

// Conflict-free staging permutation for the mirror-tile transpose.
// P maps an arithmetic progression of step 4 onto all residues mod 32.
__device__ __forceinline__ int permP(int x) {
    return ((x >> 2) | ((x & 3) << 5)) & 127;
}
__device__ __forceinline__ int cidx(int m, int n) {
    return (permP(m) + permP(n)) & 127;
}

// ---------------------------------------------------------------------------
// Main kernel: 128x128 output tile per block, only bx >= by computed; the
// symmetric mirror tile is written via an smem-staged transpose.
// smem: As[k][m], Bs[k][n] k-major (loaded from g_zT, fully coalesced +
// conflict-free STS.128). 512 threads, thread tile 8(m) x 4(n).
// ---------------------------------------------------------------------------
extern __shared__ float smem[];

__global__ __launch_bounds__(THREADS, 1)
void pairsim_kernel(float* __restrict__ out) {
    const int bx = blockIdx.x, by = blockIdx.y;
    if (bx < by) return;                       // lower-triangle blocks exit
    const int brow = by * BM;
    const int bcol = bx * BN;

    float* As = smem;             // [128][128] : As[k*BM + m]
    float* Bs = smem + BM * D;    // [128][128] : Bs[k*BN + n]

    const int tid = threadIdx.x;
    const int tx = tid & 31;      // 0..31 -> n
    const int ty = tid >> 5;      // 0..15 (warp id) -> m
    const int tm = ty * 8;
    const int tn = tx * 4;

    // Load both tiles (k-major, from pre-transposed z). 4096 float4 each.
    #pragma unroll
    for (int r = 0; r < 8; ++r) {
        int idx = tid + r * THREADS;           // 0..4095
        int k  = idx >> 5;
        int mc = (idx & 31) << 2;
        *(float4*)&As[k * BM + mc] = *(const float4*)&g_zT[k * N + brow + mc];
        *(float4*)&Bs[k * BN + mc] = *(const float4*)&g_zT[k * N + bcol + mc];
    }
    __syncthreads();

    unsigned long long c2[8][2];
    #pragma unroll
    for (int i = 0; i < 8; ++i) { c2[i][0] = 0ull; c2[i][1] = 0ull; }

    // Main loop over full K=128. FMA-pipe bound: 16 FFMA2 / thread / k.
    #pragma unroll 8
    for (int k = 0; k < D; ++k) {
        float4 a0 = *(const float4*)&As[k * BM + tm];
        float4 a1 = *(const float4*)&As[k * BM + tm + 4];
        ulonglong2 bp = *(const ulonglong2*)&Bs[k * BN + tn];
        float av[8] = {a0.x, a0.y, a0.z, a0.w, a1.x, a1.y, a1.z, a1.w};
        #pragma unroll
        for (int i = 0; i < 8; ++i) {
            unsigned long long pa = pack2(av[i]);
            ffma2(c2[i][0], pa, bp.x);
            ffma2(c2[i][1], pa, bp.y);
        }
    }

    // Epilogue.
    float sqa[8], sqb[4];
    #pragma unroll
    for (int i = 0; i < 8; ++i) sqa[i] = g_sq[brow + tm + i];
    #pragma unroll
    for (int j = 0; j < 4; ++j) sqb[j] = g_sq[bcol + tn + j];

    const bool mirror = (bx != by);

    // All threads must be done reading As/Bs before we reuse smem as staging.
    __syncthreads();

    #pragma unroll
    for (int i = 0; i < 8; ++i) {
        float c[4];
        c[0] = __uint_as_float((unsigned)(c2[i][0]));
        c[1] = __uint_as_float((unsigned)(c2[i][0] >> 32));
        c[2] = __uint_as_float((unsigned)(c2[i][1]));
        c[3] = __uint_as_float((unsigned)(c2[i][1] >> 32));
        float4 v;
        float vv[4];
        #pragma unroll
        for (int j = 0; j < 4; ++j) {
            float d2 = fmaxf(sqa[i] + sqb[j] - 2.0f * c[j], 0.0f);
            // exp underflows to 0 for d2 > ~88 (matches fp32 reference);
            // predicate keeps MUFU idle for ~all elements.
            vv[j] = (d2 < 88.0f) ? __expf(-d2) : 0.0f;
        }
        v.x = vv[0]; v.y = vv[1]; v.z = vv[2]; v.w = vv[3];
        // Own tile: coalesced STG.128.
        *(float4*)&out[(long)(brow + tm + i) * N + bcol + tn] = v;
        // Stage post-exp values for the mirror tile (conflict-free perm).
        if (mirror) {
            int m = tm + i;
            #pragma unroll
            for (int j = 0; j < 4; ++j)
                smem[m * 128 + cidx(m, tn + j)] = vv[j];
        }
    }

    if (mirror) {
        __syncthreads();
        // Write transposed tile to the symmetric block position, coalesced.
        #pragma unroll
        for (int r = 0; r < 8; ++r) {
            int idx = tid + r * THREADS;       // 0..4095
            int n  = idx >> 5;                 // mirror row within tile
            int mc = (idx & 31) << 2;          // mirror col chunk
            float4 w;
            w.x = smem[(mc + 0) * 128 + cidx(mc + 0, n)];
            w.y = smem[(mc + 1) * 128 + cidx(mc + 1, n)];
            w.z = smem[(mc + 2) * 128 + cidx(mc + 2, n)];
            w.w = smem[(mc + 3) * 128 + cidx(mc + 3, n)];
            *(float4*)&out[(long)(bcol + n) * N + brow + mc] = w;
        }
    }
}

// ---------------------------------------------------------------------------
extern "C" void kernel_launch(void* const* d_in, const int* in_sizes, int n_in,
                              void* d_out, int out_size) {
    const float* z = (const float*)d_in[0];
    float* out = (float*)d_out;
    (void)in_sizes; (void)n_in; (void)out_size;

    static_assert(2 * BM * D * sizeof(float) == 131072, "smem size");
    cudaFuncSetAttribute(pairsim_kernel,
                         cudaFuncAttributeMaxDynamicSharedMemorySize, 131072);

    prep_kernel<<<N, D>>>(z);
    dim3 grid(N / BN, N / BM);
    pairsim_kernel<<<grid, THREADS, 131072>>>(out);
}

// round 3
// speedup vs baseline: 3.0492x; 3.0492x over previous
#include <cuda_runtime.h>
#include <cuda_bf16.h>
#include <cstdint>

#define NROW 8192
#define DDIM 128
#define THREADS 256

// Scratch: bf16 copy of z and fp32 squared norms.
__device__ __nv_bfloat16 g_zbf[NROW * DDIM];
__device__ float g_sq[NROW];

// ---------------------------------------------------------------------------
// SMEM layout. Row stride 272B (128 bf16 + 8 pad) keeps ldmatrix conflict-free.
// ---------------------------------------------------------------------------
#define ROWB 272
#define SM_A 0
#define SM_B (128 * ROWB)            /* 34816 */
#define SM_STAGE 0                   /* reuse A/B after MMA: 128*132*4=67584 */
#define SM_SQA (2 * 128 * ROWB)      /* 69632 */
#define SM_SQB (SM_SQA + 512)
#define SMEM_BYTES (SM_SQB + 512)    /* 70656 */
#define STG_STRIDE 132

__device__ __forceinline__ uint32_t smem_u32(const void* p) {
    uint32_t a;
    asm("{ .reg .u64 t; cvta.to.shared.u64 t, %1; cvt.u32.u64 %0, t; }"
        : "=r"(a) : "l"(p));
    return a;
}

__device__ __forceinline__ void ldsm4(uint32_t addr, uint32_t r[4]) {
    asm volatile("ldmatrix.sync.aligned.m8n8.x4.shared.b16 {%0,%1,%2,%3}, [%4];"
                 : "=r"(r[0]), "=r"(r[1]), "=r"(r[2]), "=r"(r[3]) : "r"(addr));
}

__device__ __forceinline__ void mma16816(float c[4], const uint32_t a[4],
                                         uint32_t b0, uint32_t b1) {
    asm volatile(
        "mma.sync.aligned.m16n8k16.row.col.f32.bf16.bf16.f32 "
        "{%0,%1,%2,%3}, {%4,%5,%6,%7}, {%8,%9}, {%0,%1,%2,%3};"
        : "+f"(c[0]), "+f"(c[1]), "+f"(c[2]), "+f"(c[3])
        : "r"(a[0]), "r"(a[1]), "r"(a[2]), "r"(a[3]), "r"(b0), "r"(b1));
}

// ---------------------------------------------------------------------------
// Prep: bf16 convert + squared norms.
// ---------------------------------------------------------------------------
__global__ void prep_kernel(const float* __restrict__ z) {
    int row = blockIdx.x, t = threadIdx.x;
    float v = z[row * DDIM + t];
    g_zbf[row * DDIM + t] = __float2bfloat16(v);
    float s = v * v;
    #pragma unroll
    for (int off = 16; off > 0; off >>= 1) s += __shfl_xor_sync(~0u, s, off);
    __shared__ float ws[4];
    if ((t & 31) == 0) ws[t >> 5] = s;
    __syncthreads();
    if (t == 0) g_sq[row] = ws[0] + ws[1] + ws[2] + ws[3];
}

// ---------------------------------------------------------------------------
// Main kernel: 128x128 tile per CTA via mma.sync bf16. 8 warps in a 4x2 grid,
// each computes 32(m) x 64(n). Only bx >= by tiles run; mirror tile written
// via SMEM-staged transpose.
// ---------------------------------------------------------------------------
extern __shared__ char smem[];

__global__ __launch_bounds__(THREADS, 2)
void pairsim_mma(float* __restrict__ out) {
    const int bx = blockIdx.x, by = blockIdx.y;
    if (bx < by) return;
    const int brow = by * 128, bcol = bx * 128;
    const uint32_t sb = smem_u32(smem);
    const int tid = threadIdx.x, wid = tid >> 5, lane = tid & 31;
    const int wr = wid & 3, wc = wid >> 2;

    float* SQA = (float*)(smem + SM_SQA);
    float* SQB = (float*)(smem + SM_SQB);
    if (tid < 128) SQA[tid] = g_sq[brow + tid];
    else           SQB[tid - 128] = g_sq[bcol + tid - 128];

    // Load A (rows brow..+127) and B (rows bcol..+127) tiles, 16B chunks.
    #pragma unroll
    for (int it = 0; it < 8; ++it) {
        int idx = tid + it * THREADS;      // 0..2047
        int r = idx >> 4, kc = (idx & 15) << 3;
        *(uint4*)(smem + SM_A + r * ROWB + kc * 2) =
            *(const uint4*)&g_zbf[(size_t)(brow + r) * DDIM + kc];
        *(uint4*)(smem + SM_B + r * ROWB + kc * 2) =
            *(const uint4*)&g_zbf[(size_t)(bcol + r) * DDIM + kc];
    }
    __syncthreads();

    // ldmatrix lane base addresses.
    // A x4: lanes 0-15 -> rows m0-15 @k0; 16-31 -> rows m0-15 @k+16B.
    const uint32_t aBase = sb + SM_A + (wr * 32 + (lane & 15)) * ROWB
                         + ((lane >> 4) << 4);
    // B x4 (two n-tiles): l0-7 n0-7@k0; l8-15 n0-7@+16B; l16-23 n8-15@k0; l24-31 n8-15@+16B.
    const uint32_t bBase = sb + SM_B
                         + (wc * 64 + ((lane & 7) | ((lane >> 4) << 3))) * ROWB
                         + (((lane >> 3) & 1) << 4);

    float acc[2][8][4];
    #pragma unroll
    for (int mt = 0; mt < 2; ++mt)
        #pragma unroll
        for (int nt = 0; nt < 8; ++nt)
            #pragma unroll
            for (int c = 0; c < 4; ++c) acc[mt][nt][c] = 0.0f;

    #pragma unroll
    for (int ks = 0; ks < 8; ++ks) {
        uint32_t aF[2][4], bF[4][4];
        ldsm4(aBase + ks * 32, aF[0]);
        ldsm4(aBase + 16 * ROWB + ks * 32, aF[1]);
        #pragma unroll
        for (int p = 0; p < 4; ++p) ldsm4(bBase + p * 16 * ROWB + ks * 32, bF[p]);
        #pragma unroll
        for (int mt = 0; mt < 2; ++mt)
            #pragma unroll
            for (int p = 0; p < 4; ++p) {
                mma16816(acc[mt][2 * p],     aF[mt], bF[p][0], bF[p][1]);
                mma16816(acc[mt][2 * p + 1], aF[mt], bF[p][2], bF[p][3]);
            }
    }

    // Epilogue: d2 = sqa + sqb - 2*gram; exp with underflow fast-path.
    const int qr = lane >> 2;            // 0..7
    const int qc = (lane & 3) << 1;      // 0,2,4,6
    float sqa_r[4], sqb_c[16];
    #pragma unroll
    for (int mt = 0; mt < 2; ++mt)
        #pragma unroll
        for (int h = 0; h < 2; ++h)
            sqa_r[mt * 2 + h] = SQA[wr * 32 + mt * 16 + qr + h * 8];
    #pragma unroll
    for (int nt = 0; nt < 8; ++nt) {
        sqb_c[2 * nt]     = SQB[wc * 64 + nt * 8 + qc];
        sqb_c[2 * nt + 1] = SQB[wc * 64 + nt * 8 + qc + 1];
    }

    float vmin = 3.4e38f;
    #pragma unroll
    for (int mt = 0; mt < 2; ++mt)
        #pragma unroll
        for (int nt = 0; nt < 8; ++nt)
            #pragma unroll
            for (int c = 0; c < 4; ++c) {
                float s = sqa_r[mt * 2 + (c >> 1)] + sqb_c[2 * nt + (c & 1)];
                float d2 = fmaf(-2.0f, acc[mt][nt][c], s);
                acc[mt][nt][c] = d2;
                vmin = fminf(vmin, d2);
            }

    if (__any_sync(0xffffffffu, vmin < 88.0f)) {
        #pragma unroll
        for (int mt = 0; mt < 2; ++mt)
            #pragma unroll
            for (int nt = 0; nt < 8; ++nt)
                #pragma unroll
                for (int c = 0; c < 4; ++c) {
                    float d2 = fmaxf(acc[mt][nt][c], 0.0f);
                    float v = (d2 < 88.0f) ? __expf(-d2) : 0.0f;
                    int m = brow + wr * 32 + mt * 16 + qr + ((c >> 1) << 3);
                    int n = bcol + wc * 64 + nt * 8 + qc + (c & 1);
                    if (m == n) v = 1.0f;       // exact diagonal
                    acc[mt][nt][c] = v;
                }
    } else {
        #pragma unroll
        for (int mt = 0; mt < 2; ++mt)
            #pragma unroll
            for (int nt = 0; nt < 8; ++nt)
                #pragma unroll
                for (int c = 0; c < 4; ++c) acc[mt][nt][c] = 0.0f;
    }

    // Direct tile: 8B vector stores (full 32B sectors per quad).
    #pragma unroll
    for (int mt = 0; mt < 2; ++mt)
        #pragma unroll
        for (int h = 0; h < 2; ++h) {
            int m_loc = wr * 32 + mt * 16 + qr + h * 8;
            size_t rowp = (size_t)(brow + m_loc) * NROW + bcol + wc * 64;
            #pragma unroll
            for (int nt = 0; nt < 8; ++nt)
                *(float2*)&out[rowp + nt * 8 + qc] =
                    make_float2(acc[mt][nt][2 * h], acc[mt][nt][2 * h + 1]);
        }

    // Mirror tile via staged transpose (skip on diagonal tiles).
    if (bx != by) {
        __syncthreads();                 // everyone done reading A/B smem
        float* stg = (float*)(smem + SM_STAGE);
        #pragma unroll
        for (int mt = 0; mt < 2; ++mt)
            #pragma unroll
            for (int h = 0; h < 2; ++h) {
                int m_loc = wr * 32 + mt * 16 + qr + h * 8;
                #pragma unroll
                for (int nt = 0; nt < 8; ++nt) {
                    int n_loc = wc * 64 + nt * 8 + qc;
                    stg[(n_loc)     * STG_STRIDE + m_loc] = acc[mt][nt][2 * h];
                    stg[(n_loc + 1) * STG_STRIDE + m_loc] = acc[mt][nt][2 * h + 1];
                }
            }
        __syncthreads();
        #pragma unroll
        for (int it = 0; it < 16; ++it) {
            int idx = tid + it * THREADS;      // 0..4095
            int n = idx >> 5, c4 = (idx & 31) << 2;
            float4 v = *(float4*)&stg[n * STG_STRIDE + c4];
            *(float4*)&out[(size_t)(bcol + n) * NROW + brow + c4] = v;
        }
    }
}

// ---------------------------------------------------------------------------
extern "C" void kernel_launch(void* const* d_in, const int* in_sizes, int n_in,
                              void* d_out, int out_size) {
    const float* z = (const float*)d_in[0];
    float* out = (float*)d_out;
    (void)in_sizes; (void)n_in; (void)out_size;

    cudaFuncSetAttribute(pairsim_mma,
                         cudaFuncAttributeMaxDynamicSharedMemorySize, SMEM_BYTES);

    prep_kernel<<<NROW, DDIM>>>(z);
    dim3 grid(64, 64);
    pairsim_mma<<<grid, THREADS, SMEM_BYTES>>>(out);
}